// round 2
// baseline (speedup 1.0000x reference)
#include <cuda_runtime.h>
#include <math.h>

// Blinn-Phong: per point i, inputs[i] = {light[3], normal[3], view[3]} (AoS, 9 fp32).
// out[i][c] = ks[c] * pow(max(0, dot(n, normalize(l+v))), p) + kd[c] * max(0, dot(l, n))
//
// Strategy: pure HBM-bound elementwise. Stage each block's 256-point (9216 B)
// region through shared memory with fully-coalesced float4 loads/stores so every
// global transaction is a full line; per-thread smem access is stride-9 / stride-3
// (both coprime with 32 banks -> conflict-free).

#define PTS 256            // points per block == threads per block
#define EPS 1e-12f

__global__ __launch_bounds__(PTS) void blinn_phong_kernel(
    const float* __restrict__ inp,   // [n, 3, 3]
    const float* __restrict__ kd,    // [3]
    const float* __restrict__ ks,    // [3]
    const float* __restrict__ pp,    // [1]
    float* __restrict__ out,         // [n, 3]
    int n)
{
    __shared__ float s_in[PTS * 9];   // 9216 B
    __shared__ float s_out[PTS * 3];  // 3072 B

    const int tid = threadIdx.x;
    const long long block_pt0 = (long long)blockIdx.x * PTS;
    const int pts_here = (int)min((long long)PTS, (long long)n - block_pt0);
    if (pts_here <= 0) return;

    // ---- coalesced load: pts_here*9 floats as float4 where possible ----
    {
        const float* gbase = inp + block_pt0 * 9;
        const int nfloats = pts_here * 9;
        const int nvec4 = nfloats >> 2;           // full float4s
        const float4* g4 = (const float4*)gbase;  // base is 36B*256-aligned per block when full
        float4* s4 = (float4*)s_in;
        // base alignment: block_pt0*9*4 bytes = blockIdx.x*9216 -> 16B aligned. OK.
        for (int i = tid; i < nvec4; i += PTS) s4[i] = g4[i];
        // tail floats (only possible on last partial block)
        for (int i = (nvec4 << 2) + tid; i < nfloats; i += PTS) s_in[i] = gbase[i];
    }
    __syncthreads();

    // ---- compute (one point per thread) ----
    const float kd0 = kd[0], kd1 = kd[1], kd2 = kd[2];
    const float ks0 = ks[0], ks1 = ks[1], ks2 = ks[2];
    const float p = pp[0];

    if (tid < pts_here) {
        const float* q = &s_in[tid * 9];
        float lx = q[0], ly = q[1], lz = q[2];
        float nx = q[3], ny = q[4], nz = q[5];
        float vx = q[6], vy = q[7], vz = q[8];

        // diffuse term: max(0, dot(l, n))
        float ln = fmaxf(0.0f, fmaf(lx, nx, fmaf(ly, ny, lz * nz)));

        // half vector h = l + v, normalized
        float hx = lx + vx, hy = ly + vy, hz = lz + vz;
        float h2 = fmaf(hx, hx, fmaf(hy, hy, hz * hz));
        float norm = fmaxf(sqrtf(h2), EPS);
        float inv = 1.0f / norm;

        // specular: max(0, dot(n, half))^p
        float nh = fmaxf(0.0f, fmaf(nx, hx, fmaf(ny, hy, nz * hz)) * inv);
        // pow(nh, p): nh==0 -> log2f(0) = -inf -> exp2f(-inf) = 0 (matches jnp.power)
        float spec = exp2f(p * log2f(nh));

        float* o = &s_out[tid * 3];
        o[0] = fmaf(ks0, spec, kd0 * ln);
        o[1] = fmaf(ks1, spec, kd1 * ln);
        o[2] = fmaf(ks2, spec, kd2 * ln);
    }
    __syncthreads();

    // ---- coalesced store: pts_here*3 floats as float4 where possible ----
    {
        float* gbase = out + block_pt0 * 3;
        const int nfloats = pts_here * 3;
        const int nvec4 = nfloats >> 2;
        float4* g4 = (float4*)gbase;               // block_pt0*3*4 = blockIdx.x*3072 -> 16B aligned
        const float4* s4 = (const float4*)s_out;
        for (int i = tid; i < nvec4; i += PTS) g4[i] = s4[i];
        for (int i = (nvec4 << 2) + tid; i < nfloats; i += PTS) gbase[i] = s_out[i];
    }
}

extern "C" void kernel_launch(void* const* d_in, const int* in_sizes, int n_in,
                              void* d_out, int out_size)
{
    const float* inp = (const float*)d_in[0];
    const float* kd  = (const float*)d_in[1];
    const float* ks  = (const float*)d_in[2];
    const float* p   = (const float*)d_in[3];
    float* out = (float*)d_out;

    const int n = in_sizes[0] / 9;
    const int grid = (n + PTS - 1) / PTS;
    blinn_phong_kernel<<<grid, PTS>>>(inp, kd, ks, p, out, n);
}

// round 3
// speedup vs baseline: 1.6673x; 1.6673x over previous
#include <cuda_runtime.h>
#include <math.h>

// Blinn-Phong, N points, AoS input [n,3,3] = {light, normal, view} fp32.
// out[i][c] = ks[c]*pow(max(0, n.h/|h|), p) + kd[c]*max(0, l.n),  h = l+v
//
// R2: (a) p==16 fast path: spec = ((n.h)^2/|h|^2)^8 -> 1 MUFU (RCP) + 3 muls,
//     removing the MUFU bottleneck (was ~4 MUFU/pt: rsqrt,rcp,lg2,ex2).
//     (b) 1024 pts/block, 256 thr: load loop is exactly 9 unrolled LDG.128
//     per thread (high MLP), store is 3 unrolled STG.128. Smem staging keeps
//     all global traffic as full 128B lines; strided point assignment keeps
//     smem stride-9 / stride-3 (coprime with 32 banks -> conflict-free).

#define THREADS 256
#define TILE    1024                 // points per block (4 per thread)
#define EPS 1e-12f

__global__ __launch_bounds__(THREADS) void blinn_phong_kernel(
    const float* __restrict__ inp,   // [n, 3, 3]
    const float* __restrict__ kd,    // [3]
    const float* __restrict__ ks,    // [3]
    const float* __restrict__ pp,    // [1]
    float* __restrict__ out,         // [n, 3]
    int n)
{
    __shared__ float s_in[TILE * 9];   // 36 KB
    __shared__ float s_out[TILE * 3];  // 12 KB

    const int tid = threadIdx.x;
    const long long pt0 = (long long)blockIdx.x * TILE;
    const int pts_here = (int)min((long long)TILE, (long long)n - pt0);
    if (pts_here <= 0) return;

    const bool full = (pts_here == TILE);

    // ---- load: TILE*9 floats = TILE*9/4 float4 (9 per thread, unrolled) ----
    {
        const float4* g4 = (const float4*)(inp + pt0 * 9);  // 16B aligned (pt0*36 B)
        float4* s4 = (float4*)s_in;
        if (full) {
            #pragma unroll
            for (int i = 0; i < (TILE * 9 / 4) / THREADS; i++)
                s4[tid + i * THREADS] = g4[tid + i * THREADS];
        } else {
            const int nf = pts_here * 9;
            const int nv = nf >> 2;
            for (int i = tid; i < nv; i += THREADS) s4[i] = g4[i];
            const float* gf = inp + pt0 * 9;
            for (int i = (nv << 2) + tid; i < nf; i += THREADS) s_in[i] = gf[i];
        }
    }
    __syncthreads();

    // ---- compute: 4 points per thread, strided by THREADS ----
    const float kd0 = kd[0], kd1 = kd[1], kd2 = kd[2];
    const float ks0 = ks[0], ks1 = ks[1], ks2 = ks[2];
    const float p = pp[0];
    const bool p16 = (p == 16.0f);

    #pragma unroll
    for (int j = 0; j < TILE / THREADS; j++) {
        const int pt = tid + j * THREADS;
        if (full || pt < pts_here) {
            const float* q = &s_in[pt * 9];
            float lx = q[0], ly = q[1], lz = q[2];
            float nx = q[3], ny = q[4], nz = q[5];
            float vx = q[6], vy = q[7], vz = q[8];

            // diffuse: max(0, l.n)
            float ln = fmaxf(0.0f, fmaf(lx, nx, fmaf(ly, ny, lz * nz)));

            // half vector (unnormalized)
            float hx = lx + vx, hy = ly + vy, hz = lz + vz;
            float h2 = fmaf(hx, hx, fmaf(hy, hy, hz * hz));
            float d  = fmaf(nx, hx, fmaf(ny, hy, nz * hz));   // n.h (unnormalized)

            float spec;
            if (p16) {
                // (d/|h|)^16 = (d^2/h^2)^8 ; d<=0 or h2==0 -> 0
                float t  = __fdividef(d * d, h2);
                float t2 = t * t;
                float t4 = t2 * t2;
                spec = t4 * t4;
                spec = (d > 0.0f) ? spec : 0.0f;
            } else {
                float norm = fmaxf(sqrtf(h2), EPS);
                float nh = fmaxf(0.0f, d / norm);
                spec = exp2f(p * log2f(nh));   // nh==0 -> -inf -> 0
            }

            float* o = &s_out[pt * 3];
            o[0] = fmaf(ks0, spec, kd0 * ln);
            o[1] = fmaf(ks1, spec, kd1 * ln);
            o[2] = fmaf(ks2, spec, kd2 * ln);
        }
    }
    __syncthreads();

    // ---- store: TILE*3 floats = TILE*3/4 float4 (3 per thread, unrolled) ----
    {
        float4* g4 = (float4*)(out + pt0 * 3);   // 16B aligned (pt0*12 B)
        const float4* s4 = (const float4*)s_out;
        if (full) {
            #pragma unroll
            for (int i = 0; i < (TILE * 3 / 4) / THREADS; i++)
                g4[tid + i * THREADS] = s4[tid + i * THREADS];
        } else {
            const int nf = pts_here * 3;
            const int nv = nf >> 2;
            for (int i = tid; i < nv; i += THREADS) g4[i] = s4[i];
            float* gf = out + pt0 * 3;
            for (int i = (nv << 2) + tid; i < nf; i += THREADS) gf[i] = s_out[i];
        }
    }
}

extern "C" void kernel_launch(void* const* d_in, const int* in_sizes, int n_in,
                              void* d_out, int out_size)
{
    const float* inp = (const float*)d_in[0];
    const float* kd  = (const float*)d_in[1];
    const float* ks  = (const float*)d_in[2];
    const float* p   = (const float*)d_in[3];
    float* out = (float*)d_out;

    const int n = in_sizes[0] / 9;
    const int grid = (n + TILE - 1) / TILE;
    blinn_phong_kernel<<<grid, THREADS>>>(inp, kd, ks, p, out, n);
}

// round 4
// speedup vs baseline: 1.7035x; 1.0218x over previous
#include <cuda_runtime.h>
#include <math.h>

// Blinn-Phong, N points, AoS input [n,3,3] = {light, normal, view} fp32.
// out[i][c] = ks[c]*pow(max(0, n.h/|h|), p) + kd[c]*max(0, l.n),  h = l+v
//
// R3: smem cut 48KB -> 36KB by aliasing the output staging region into s_in
//     (results held in registers across a barrier), raising occupancy
//     4 -> 6 CTAs/SM. Streaming cache hints (__ldcs/__stcs): 201MB streams
//     once through a 126MB L2, so evict-first on both directions.
//     Memory shape unchanged: 9 unrolled LDG.128 + 3 STG.128 per thread,
//     all full 128B lines; smem stride-9 / stride-3 conflict-free.

#define THREADS 256
#define TILE    1024                 // points per block (4 per thread)
#define EPS 1e-12f

__global__ __launch_bounds__(THREADS) void blinn_phong_kernel(
    const float* __restrict__ inp,   // [n, 3, 3]
    const float* __restrict__ kd,    // [3]
    const float* __restrict__ ks,    // [3]
    const float* __restrict__ pp,    // [1]
    float* __restrict__ out,         // [n, 3]
    int n)
{
    __shared__ float s_in[TILE * 9];           // 36 KB; first TILE*3 reused as out-stage

    const int tid = threadIdx.x;
    const long long pt0 = (long long)blockIdx.x * TILE;
    const int pts_here = (int)min((long long)TILE, (long long)n - pt0);
    if (pts_here <= 0) return;

    const bool full = (pts_here == TILE);

    // ---- load: TILE*9 floats as 9 unrolled LDG.128 per thread ----
    {
        const float4* g4 = (const float4*)(inp + pt0 * 9);  // pt0*36 B -> 16B aligned
        float4* s4 = (float4*)s_in;
        if (full) {
            #pragma unroll
            for (int i = 0; i < (TILE * 9 / 4) / THREADS; i++)
                s4[tid + i * THREADS] = __ldcs(&g4[tid + i * THREADS]);
        } else {
            const int nf = pts_here * 9;
            const int nv = nf >> 2;
            for (int i = tid; i < nv; i += THREADS) s4[i] = __ldcs(&g4[i]);
            const float* gf = inp + pt0 * 9;
            for (int i = (nv << 2) + tid; i < nf; i += THREADS) s_in[i] = gf[i];
        }
    }
    __syncthreads();

    // ---- compute: 4 points per thread into registers ----
    const float kd0 = kd[0], kd1 = kd[1], kd2 = kd[2];
    const float ks0 = ks[0], ks1 = ks[1], ks2 = ks[2];
    const float p = pp[0];
    const bool p16 = (p == 16.0f);

    float res[(TILE / THREADS) * 3];

    #pragma unroll
    for (int j = 0; j < TILE / THREADS; j++) {
        const int pt = tid + j * THREADS;
        if (full || pt < pts_here) {
            const float* q = &s_in[pt * 9];
            float lx = q[0], ly = q[1], lz = q[2];
            float nx = q[3], ny = q[4], nz = q[5];
            float vx = q[6], vy = q[7], vz = q[8];

            // diffuse: max(0, l.n)
            float ln = fmaxf(0.0f, fmaf(lx, nx, fmaf(ly, ny, lz * nz)));

            // half vector (unnormalized)
            float hx = lx + vx, hy = ly + vy, hz = lz + vz;
            float h2 = fmaf(hx, hx, fmaf(hy, hy, hz * hz));
            float d  = fmaf(nx, hx, fmaf(ny, hy, nz * hz));   // n.h (unnormalized)

            float spec;
            if (p16) {
                // (d/|h|)^16 = (d^2/h^2)^8 ; d<=0 -> 0
                float t  = __fdividef(d * d, h2);
                float t2 = t * t;
                float t4 = t2 * t2;
                spec = t4 * t4;
                spec = (d > 0.0f) ? spec : 0.0f;
            } else {
                float norm = fmaxf(sqrtf(h2), EPS);
                float nh = fmaxf(0.0f, d / norm);
                spec = exp2f(p * log2f(nh));   // nh==0 -> -inf -> 0
            }

            res[j * 3 + 0] = fmaf(ks0, spec, kd0 * ln);
            res[j * 3 + 1] = fmaf(ks1, spec, kd1 * ln);
            res[j * 3 + 2] = fmaf(ks2, spec, kd2 * ln);
        }
    }
    __syncthreads();   // all smem reads complete before aliasing as out-stage

    // ---- stage results into s_in[0 .. TILE*3) (stride-3: conflict-free) ----
    #pragma unroll
    for (int j = 0; j < TILE / THREADS; j++) {
        const int pt = tid + j * THREADS;
        if (full || pt < pts_here) {
            s_in[pt * 3 + 0] = res[j * 3 + 0];
            s_in[pt * 3 + 1] = res[j * 3 + 1];
            s_in[pt * 3 + 2] = res[j * 3 + 2];
        }
    }
    __syncthreads();

    // ---- store: TILE*3 floats as 3 unrolled STG.128 per thread ----
    {
        float4* g4 = (float4*)(out + pt0 * 3);   // pt0*12 B -> 16B aligned
        const float4* s4 = (const float4*)s_in;
        if (full) {
            #pragma unroll
            for (int i = 0; i < (TILE * 3 / 4) / THREADS; i++)
                __stcs(&g4[tid + i * THREADS], s4[tid + i * THREADS]);
        } else {
            const int nf = pts_here * 3;
            const int nv = nf >> 2;
            for (int i = tid; i < nv; i += THREADS) __stcs(&g4[i], s4[i]);
            float* gf = out + pt0 * 3;
            for (int i = (nv << 2) + tid; i < nf; i += THREADS) gf[i] = s_in[i];
        }
    }
}

extern "C" void kernel_launch(void* const* d_in, const int* in_sizes, int n_in,
                              void* d_out, int out_size)
{
    const float* inp = (const float*)d_in[0];
    const float* kd  = (const float*)d_in[1];
    const float* ks  = (const float*)d_in[2];
    const float* p   = (const float*)d_in[3];
    float* out = (float*)d_out;

    const int n = in_sizes[0] / 9;
    const int grid = (n + TILE - 1) / TILE;
    blinn_phong_kernel<<<grid, THREADS>>>(inp, kd, ks, p, out, n);
}